// round 1
// baseline (speedup 1.0000x reference)
#include <cuda_runtime.h>
#include <cuda_bf16.h>

// Problem: out[i,j,o] = sum_h x[i+1,h]*x[j+1,h]*W[o,h] + b[o]
//   (the diff/W2 term is antisymmetric and cancels under the (P+P^T)/2
//    symmetrization in the reference; the prod term is already symmetric)
// x: (512, 768) f32, W: (2, 1536) f32 (only first 768 cols used), b: (2,) f32
// out: (510, 510, 2) f32
//
// Strategy: Y_o = (X .* w_o) X^T, symmetric -> compute only upper-tri 32x32
// tiles (136 of 256 blocks live ~= one wave on 148 SMs), mirror-write.

#define HDIM 768
#define NOUT 510
#define BM 32
#define BN 32
#define BK 32

__global__ __launch_bounds__(256, 4)
void pairwise_head_kernel(const float* __restrict__ x,
                          const float* __restrict__ W,
                          const float* __restrict__ bias,
                          float* __restrict__ out)
{
    const int bi = blockIdx.y;
    const int bj = blockIdx.x;
    if (bj < bi) return;   // symmetric: only upper-triangular tile pairs

    __shared__ float ws0[HDIM];
    __shared__ float ws1[HDIM];
    __shared__ float Aw0[BK][BM + 1];   // x_i * w0, stored [k][m]
    __shared__ float Aw1[BK][BM + 1];   // x_i * w1
    __shared__ float Bt [BK][BN + 1];   // x_j,      stored [k][n]

    const int tid = threadIdx.x;

    // Preload both W1 rows once (6 KB)
    for (int h = tid; h < HDIM; h += 256) {
        ws0[h] = W[h];          // W[0, 0:768]
        ws1[h] = W[1536 + h];   // W[1, 0:768]
    }
    __syncthreads();

    const int ibase = bi * BM;
    const int jbase = bj * BN;

    // Loader mapping: 256 threads cover 32 rows x 8 float4 per tile
    const int lr = tid >> 3;          // row within tile, 0..31
    const int lk = (tid & 7) * 4;     // k offset within chunk, 0..28

    // Compute mapping: 16x16 thread grid, 2x2 micro-tile
    const int tx = tid & 15;
    const int ty = tid >> 4;
    const int m0 = ty, m1 = ty + 16;
    const int n0 = tx, n1 = tx + 16;

    float a00 = 0.f, a01 = 0.f, a10 = 0.f, a11 = 0.f;  // channel 0
    float c00 = 0.f, c01 = 0.f, c10 = 0.f, c11 = 0.f;  // channel 1

    const int gi_load = ibase + lr;
    const int gj_load = jbase + lr;

    for (int k0 = 0; k0 < HDIM; k0 += BK) {
        // Global loads (x rows shifted by +1 for the [1:-1] crop)
        float4 av = make_float4(0.f, 0.f, 0.f, 0.f);
        float4 bv = make_float4(0.f, 0.f, 0.f, 0.f);
        if (gi_load < NOUT)
            av = *reinterpret_cast<const float4*>(x + (size_t)(gi_load + 1) * HDIM + k0 + lk);
        if (gj_load < NOUT)
            bv = *reinterpret_cast<const float4*>(x + (size_t)(gj_load + 1) * HDIM + k0 + lk);

        const float w00 = ws0[k0 + lk + 0], w01 = ws0[k0 + lk + 1],
                    w02 = ws0[k0 + lk + 2], w03 = ws0[k0 + lk + 3];
        const float w10 = ws1[k0 + lk + 0], w11 = ws1[k0 + lk + 1],
                    w12 = ws1[k0 + lk + 2], w13 = ws1[k0 + lk + 3];

        __syncthreads();   // previous iteration's inner-loop reads complete

        Aw0[lk + 0][lr] = av.x * w00;
        Aw0[lk + 1][lr] = av.y * w01;
        Aw0[lk + 2][lr] = av.z * w02;
        Aw0[lk + 3][lr] = av.w * w03;
        Aw1[lk + 0][lr] = av.x * w10;
        Aw1[lk + 1][lr] = av.y * w11;
        Aw1[lk + 2][lr] = av.z * w12;
        Aw1[lk + 3][lr] = av.w * w13;
        Bt [lk + 0][lr] = bv.x;
        Bt [lk + 1][lr] = bv.y;
        Bt [lk + 2][lr] = bv.z;
        Bt [lk + 3][lr] = bv.w;

        __syncthreads();

        #pragma unroll
        for (int kk = 0; kk < BK; kk++) {
            const float p0 = Aw0[kk][m0];
            const float p1 = Aw0[kk][m1];
            const float q0 = Aw1[kk][m0];
            const float q1 = Aw1[kk][m1];
            const float r0 = Bt [kk][n0];
            const float r1 = Bt [kk][n1];
            a00 = fmaf(p0, r0, a00);
            a01 = fmaf(p0, r1, a01);
            a10 = fmaf(p1, r0, a10);
            a11 = fmaf(p1, r1, a11);
            c00 = fmaf(q0, r0, c00);
            c01 = fmaf(q0, r1, c01);
            c10 = fmaf(q1, r0, c10);
            c11 = fmaf(q1, r1, c11);
        }
    }

    const float b0 = bias[0];
    const float b1 = bias[1];

    const int gi0 = ibase + m0, gi1 = ibase + m1;
    const int gj0 = jbase + n0, gj1 = jbase + n1;

    // out[i][j][o] ... and mirror out[j][i][o] (identical value by symmetry)
    #define STORE(i, j, v0, v1)                                   \
        if ((i) < NOUT && (j) < NOUT) {                           \
            const size_t _ix = ((size_t)(i) * NOUT + (j)) * 2;    \
            out[_ix + 0] = (v0) + b0;                             \
            out[_ix + 1] = (v1) + b1;                             \
        }

    STORE(gi0, gj0, a00, c00);
    STORE(gi0, gj1, a01, c01);
    STORE(gi1, gj0, a10, c10);
    STORE(gi1, gj1, a11, c11);
    if (bi != bj) {
        STORE(gj0, gi0, a00, c00);
        STORE(gj1, gi0, a01, c01);
        STORE(gj0, gi1, a10, c10);
        STORE(gj1, gi1, a11, c11);
    }
    #undef STORE
}

extern "C" void kernel_launch(void* const* d_in, const int* in_sizes, int n_in,
                              void* d_out, int out_size)
{
    const float* x = (const float*)d_in[0];   // (1, 512, 768)
    const float* W = (const float*)d_in[1];   // (2, 1536)
    const float* b = (const float*)d_in[2];   // (2,)
    float* out = (float*)d_out;               // (1, 510, 510, 2)

    dim3 grid(16, 16);   // 32x32 tiles over 510x510; lower-tri blocks exit
    pairwise_head_kernel<<<grid, 256>>>(x, W, b, out);
}

// round 3
// speedup vs baseline: 2.1419x; 2.1419x over previous
#include <cuda_runtime.h>
#include <cuda_bf16.h>
#include <cstdint>

// out[i,j,o] = sum_h x[i+1,h]*x[j+1,h]*W[o,h] + b[o]
// (diff/W2 term is antisymmetric -> cancels under (P+P^T)/2 symmetrization)
//
// D_o = A_o B^T with A_o = X .* w_o, B = X  (512x768, fp32)
// fp32 emulated with bf16 hi/lo 3-split on mma.sync.m16n8k16 (HMMA).
// Symmetric: compute upper-triangular 64x64 tiles only, mirror-write.

#define HDIM 768
#define NKC 24                 // 768 / 32
#define ROW_BYTES 80           // 40 bf16 cols (32 data + 8 pad) -> conflict-free LDSM
#define TILE_SZ (64 * ROW_BYTES)   // 5120 B per (64 x 32) bf16 tile
#define STAGE_SZ (4 * TILE_SZ)     // Ahi, Alo, Bhi, Blo

__device__ __forceinline__ uint32_t smem_u32(const void* p) {
    uint32_t a;
    asm("{ .reg .u64 t; cvta.to.shared.u64 t, %1; cvt.u32.u64 %0, t; }"
        : "=r"(a) : "l"(p));
    return a;
}

__device__ __forceinline__ void ldsm4(uint32_t* r, uint32_t addr) {
    asm volatile("ldmatrix.sync.aligned.m8n8.x4.shared.b16 {%0,%1,%2,%3}, [%4];"
                 : "=r"(r[0]), "=r"(r[1]), "=r"(r[2]), "=r"(r[3]) : "r"(addr));
}

__device__ __forceinline__ void mma16816(float* c, const uint32_t* a,
                                         uint32_t b0, uint32_t b1) {
    asm volatile(
        "mma.sync.aligned.m16n8k16.row.col.f32.bf16.bf16.f32 "
        "{%0,%1,%2,%3}, {%4,%5,%6,%7}, {%8,%9}, {%0,%1,%2,%3};"
        : "+f"(c[0]), "+f"(c[1]), "+f"(c[2]), "+f"(c[3])
        : "r"(a[0]), "r"(a[1]), "r"(a[2]), "r"(a[3]), "r"(b0), "r"(b1));
}

union BF2U { __nv_bfloat162 b; uint32_t u; };

__device__ __forceinline__ void split4(float4 a, uint2& hi, uint2& lo) {
    BF2U h01, h23, l01, l23;
    h01.b = __floats2bfloat162_rn(a.x, a.y);
    h23.b = __floats2bfloat162_rn(a.z, a.w);
    float2 f01 = __bfloat1622float2(h01.b);
    float2 f23 = __bfloat1622float2(h23.b);
    l01.b = __floats2bfloat162_rn(a.x - f01.x, a.y - f01.y);
    l23.b = __floats2bfloat162_rn(a.z - f23.x, a.w - f23.y);
    hi = make_uint2(h01.u, h23.u);
    lo = make_uint2(l01.u, l23.u);
}

__global__ void __launch_bounds__(128)
pairwise_mma_kernel(const float* __restrict__ x,
                    const float* __restrict__ W,
                    const float* __restrict__ bias,
                    float* __restrict__ out)
{
    const int bi = blockIdx.y;
    const int bj = blockIdx.x;
    const int ch = blockIdx.z;
    if (bj < bi) return;      // symmetric output

    __shared__ __align__(16) char smem[2 * STAGE_SZ];   // 40960 B

    const int tid  = threadIdx.x;
    const int wid  = tid >> 5;
    const int lane = tid & 31;
    const int wm = wid >> 1;          // warp row (0..1), 32 rows each
    const int wn = wid & 1;           // warp col (0..1), 32 cols each

    const uint32_t sb = smem_u32(smem);

    // ---- loader mapping: 128 threads, 4 passes of 16 rows x 8 float4 ----
    const int lrow = tid >> 3;            // 0..15
    const int lc4  = tid & 7;             // float4 within 32-col chunk
    const float* xa = x + (size_t)(bi * 64 + lrow) * HDIM + lc4 * 4;
    const float* xb = x + (size_t)(bj * 64 + lrow) * HDIM + lc4 * 4;
    const float* wp = W + ch * 1536 + lc4 * 4;

    float4 rA[4], rB[4], rw;

    auto load_chunk = [&](int kc) {
        const int off = kc * 32;
        rw = *(const float4*)(wp + off);
#pragma unroll
        for (int p = 0; p < 4; p++) {
            rA[p] = *(const float4*)(xa + (size_t)p * 16 * HDIM + off);
            rB[p] = *(const float4*)(xb + (size_t)p * 16 * HDIM + off);
        }
    };

    auto sts_chunk = [&](int st) {
        char* sp = smem + st * STAGE_SZ;
#pragma unroll
        for (int p = 0; p < 4; p++) {
            const uint32_t o = (uint32_t)(lrow + p * 16) * ROW_BYTES + lc4 * 8;
            float4 a = rA[p];
            a.x *= rw.x; a.y *= rw.y; a.z *= rw.z; a.w *= rw.w;
            uint2 hA, lA, hB, lB;
            split4(a, hA, lA);
            split4(rB[p], hB, lB);
            *(uint2*)(sp + 0 * TILE_SZ + o) = hA;
            *(uint2*)(sp + 1 * TILE_SZ + o) = lA;
            *(uint2*)(sp + 2 * TILE_SZ + o) = hB;
            *(uint2*)(sp + 3 * TILE_SZ + o) = lB;
        }
    };

    float acc[2][4][4] = {};

    // ldmatrix per-lane base offsets (row = lane%16, 16B-chunk = lane/16)
    const uint32_t aoff = (uint32_t)(wm * 32 + (lane & 15)) * ROW_BYTES
                        + ((lane >> 4) << 4);
    const uint32_t boff = (uint32_t)(wn * 32 + (lane & 15)) * ROW_BYTES
                        + ((lane >> 4) << 4);

    auto compute = [&](int st) {
        const uint32_t tb = sb + st * STAGE_SZ;
#pragma unroll
        for (int h = 0; h < 2; h++) {
            const uint32_t hk = h * 32;     // byte offset of k16 half
            uint32_t ah[2][4], al[2][4], bh[2][4], bl[2][4];
            ldsm4(ah[0], tb + 0 * TILE_SZ + aoff + hk);
            ldsm4(ah[1], tb + 0 * TILE_SZ + aoff + hk + 16 * ROW_BYTES);
            ldsm4(al[0], tb + 1 * TILE_SZ + aoff + hk);
            ldsm4(al[1], tb + 1 * TILE_SZ + aoff + hk + 16 * ROW_BYTES);
            ldsm4(bh[0], tb + 2 * TILE_SZ + boff + hk);
            ldsm4(bh[1], tb + 2 * TILE_SZ + boff + hk + 16 * ROW_BYTES);
            ldsm4(bl[0], tb + 3 * TILE_SZ + boff + hk);
            ldsm4(bl[1], tb + 3 * TILE_SZ + boff + hk + 16 * ROW_BYTES);
#pragma unroll
            for (int mi = 0; mi < 2; mi++) {
#pragma unroll
                for (int nf = 0; nf < 4; nf++) {
                    // b-frag nf: ldsm result (nf>>1), pair (nf&1):
                    //   n-lo frag = {r0, r2}, n-hi frag = {r1, r3}
                    const uint32_t* BH = bh[nf >> 1];
                    const uint32_t* BL = bl[nf >> 1];
                    const int s = nf & 1;
                    float* c = acc[mi][nf];
                    mma16816(c, ah[mi], BH[s], BH[s + 2]);
                    mma16816(c, ah[mi], BL[s], BL[s + 2]);
                    mma16816(c, al[mi], BH[s], BH[s + 2]);
                }
            }
        }
    };

    // ---- pipelined main loop ----
    load_chunk(0);
    sts_chunk(0);
    __syncthreads();
#pragma unroll 1
    for (int kc = 0; kc < NKC; kc++) {
        const int st = kc & 1;
        if (kc + 1 < NKC) load_chunk(kc + 1);
        compute(st);
        if (kc + 1 < NKC) {
            sts_chunk((kc + 1) & 1);
            __syncthreads();
        }
    }

    // ---- epilogue: crop [1,510], +bias, mirror for off-diagonal tiles ----
    const float bv = bias[ch];
    const int ib = bi * 64 + wm * 32;
    const int jb = bj * 64 + wn * 32;
    const bool mirror = (bi != bj);

#pragma unroll
    for (int mi = 0; mi < 2; mi++) {
#pragma unroll
        for (int nf = 0; nf < 4; nf++) {
#pragma unroll
            for (int r = 0; r < 4; r++) {
                const int i = ib + mi * 16 + (lane >> 2) + ((r >> 1) << 3);
                const int j = jb + nf * 8 + ((lane & 3) << 1) + (r & 1);
                if (i >= 1 && i <= 510 && j >= 1 && j <= 510) {
                    const float v = acc[mi][nf][r] + bv;
                    out[((size_t)(i - 1) * 510 + (j - 1)) * 2 + ch] = v;
                    if (mirror)
                        out[((size_t)(j - 1) * 510 + (i - 1)) * 2 + ch] = v;
                }
            }
        }
    }
}

extern "C" void kernel_launch(void* const* d_in, const int* in_sizes, int n_in,
                              void* d_out, int out_size)
{
    const float* x = (const float*)d_in[0];   // (1, 512, 768)
    const float* W = (const float*)d_in[1];   // (2, 1536)
    const float* b = (const float*)d_in[2];   // (2,)
    float* out = (float*)d_out;               // (510, 510, 2)

    dim3 grid(8, 8, 2);
    pairwise_mma_kernel<<<grid, 128>>>(x, W, b, out);
}

// round 4
// speedup vs baseline: 2.2431x; 1.0472x over previous
#include <cuda_runtime.h>
#include <cuda_bf16.h>
#include <cstdint>

// out[i,j,o] = sum_h x[i+1,h]*x[j+1,h]*W[o,h] + b[o]
// (diff/W2 term is antisymmetric -> cancels under (P+P^T)/2 symmetrization)
//
// D_o = A_o B^T, A_o = X .* w_o, B = X (512x768 f32)
// fp32 emulated via bf16 hi/lo 3-split on mma.sync m16n8k16.
// Prep kernel pre-splits to bf16 images; main kernel is a pure
// cp.async -> ldmatrix -> HMMA pipeline. Upper-tri tiles + mirror.

#define HDIM 768
#define KC 64                    // k per chunk (64 bf16 = 128 B rows)
#define NKC 12                   // 768 / 64
#define ROW_B 144                // 128 B data + 16 B pad (conflict-free LDSM)
#define TILE_B (32 * ROW_B)      // 4608 B  (32 rows x 64 bf16)
#define STAGE_B (4 * TILE_B)     // Ahi, Alo, Bhi, Blo = 18432 B
#define NSTAGE 3
#define SMEM_TOTAL (NSTAGE * STAGE_B)   // 55296 B

// Pre-split bf16 images: 0:A0hi 1:A0lo 2:A1hi 3:A1lo 4:Bhi 5:Blo
__device__ __nv_bfloat16 g_pre[6][512 * HDIM];

// ---------------------------------------------------------------------------
union BF2U { __nv_bfloat162 b; uint32_t u; };
union Pack8 { __nv_bfloat16 h[8]; uint4 v; };

__device__ __forceinline__ void split8(const float* s, uint4& hi, uint4& lo) {
    Pack8 ph, pl;
#pragma unroll
    for (int t = 0; t < 8; t++) {
        __nv_bfloat16 h = __float2bfloat16(s[t]);
        ph.h[t] = h;
        pl.h[t] = __float2bfloat16(s[t] - __bfloat162float(h));
    }
    hi = ph.v; lo = pl.v;
}

__global__ void prep_kernel(const float* __restrict__ x,
                            const float* __restrict__ W)
{
    int gid = blockIdx.x * blockDim.x + threadIdx.x;
    if (gid >= 512 * (HDIM / 8)) return;
    int i  = gid / (HDIM / 8);
    int k0 = (gid % (HDIM / 8)) * 8;

    float4 x0 = *(const float4*)(x + (size_t)i * HDIM + k0);
    float4 x1 = *(const float4*)(x + (size_t)i * HDIM + k0 + 4);
    float4 wa0 = *(const float4*)(W + k0);
    float4 wa1 = *(const float4*)(W + k0 + 4);
    float4 wb0 = *(const float4*)(W + 1536 + k0);
    float4 wb1 = *(const float4*)(W + 1536 + k0 + 4);

    float xs[8] = {x0.x, x0.y, x0.z, x0.w, x1.x, x1.y, x1.z, x1.w};
    float w0[8] = {wa0.x, wa0.y, wa0.z, wa0.w, wa1.x, wa1.y, wa1.z, wa1.w};
    float w1[8] = {wb0.x, wb0.y, wb0.z, wb0.w, wb1.x, wb1.y, wb1.z, wb1.w};
    float a0[8], a1[8];
#pragma unroll
    for (int t = 0; t < 8; t++) { a0[t] = xs[t] * w0[t]; a1[t] = xs[t] * w1[t]; }

    uint4 h, l;
    size_t off = (size_t)i * HDIM + k0;
    split8(a0, h, l);
    *(uint4*)(&g_pre[0][off]) = h;  *(uint4*)(&g_pre[1][off]) = l;
    split8(a1, h, l);
    *(uint4*)(&g_pre[2][off]) = h;  *(uint4*)(&g_pre[3][off]) = l;
    split8(xs, h, l);
    *(uint4*)(&g_pre[4][off]) = h;  *(uint4*)(&g_pre[5][off]) = l;
}

// ---------------------------------------------------------------------------
__device__ __forceinline__ uint32_t smem_u32(const void* p) {
    uint32_t a;
    asm("{ .reg .u64 t; cvta.to.shared.u64 t, %1; cvt.u32.u64 %0, t; }"
        : "=r"(a) : "l"(p));
    return a;
}

__device__ __forceinline__ void cp16(uint32_t dst, const void* src) {
    asm volatile("cp.async.cg.shared.global [%0], [%1], 16;"
                 :: "r"(dst), "l"(src) : "memory");
}

__device__ __forceinline__ void ldsm4(uint32_t* r, uint32_t addr) {
    asm volatile("ldmatrix.sync.aligned.m8n8.x4.shared.b16 {%0,%1,%2,%3}, [%4];"
                 : "=r"(r[0]), "=r"(r[1]), "=r"(r[2]), "=r"(r[3]) : "r"(addr));
}

__device__ __forceinline__ void mma16816(float* c, const uint32_t* a,
                                         uint32_t b0, uint32_t b1) {
    asm volatile(
        "mma.sync.aligned.m16n8k16.row.col.f32.bf16.bf16.f32 "
        "{%0,%1,%2,%3}, {%4,%5,%6,%7}, {%8,%9}, {%0,%1,%2,%3};"
        : "+f"(c[0]), "+f"(c[1]), "+f"(c[2]), "+f"(c[3])
        : "r"(a[0]), "r"(a[1]), "r"(a[2]), "r"(a[3]), "r"(b0), "r"(b1));
}

__global__ void __launch_bounds__(128)
pairwise_mma_kernel(const float* __restrict__ bias, float* __restrict__ out)
{
    const int bi = blockIdx.y;
    const int bj = blockIdx.x;
    const int ch = blockIdx.z;
    if (bj < bi) return;      // symmetric output: upper-tri tiles only

    extern __shared__ __align__(16) char smem[];
    const uint32_t sb = smem_u32(smem);

    const int tid  = threadIdx.x;
    const int wid  = tid >> 5;
    const int lane = tid & 31;
    const int wm = wid >> 1;          // warp row (0..1) of 16
    const int wn = wid & 1;           // warp col (0..1) of 16

    // cp.async source bases (row-major bf16, HDIM stride)
    const __nv_bfloat16* src[4];
    src[0] = &g_pre[ch * 2 + 0][(size_t)(bi * 32) * HDIM];
    src[1] = &g_pre[ch * 2 + 1][(size_t)(bi * 32) * HDIM];
    src[2] = &g_pre[4][(size_t)(bj * 32) * HDIM];
    src[3] = &g_pre[5][(size_t)(bj * 32) * HDIM];

    const int lrow = tid >> 3;        // 0..15
    const int lc   = tid & 7;         // 16B chunk within 128B row

    auto issue = [&](int kc, int sl) {
        const uint32_t dbase = sb + sl * STAGE_B + lc * 16;
        const int kcol = kc * KC + lc * 8;
#pragma unroll
        for (int q = 0; q < 4; q++) {
#pragma unroll
            for (int p = 0; p < 2; p++) {
                const int row = lrow + p * 16;
                cp16(dbase + q * TILE_B + row * ROW_B,
                     src[q] + (size_t)row * HDIM + kcol);
            }
        }
    };

    float acc[2][4] = {};

    const uint32_t arow = (uint32_t)(wm * 16 + (lane & 15)) * ROW_B
                        + ((lane >> 4) << 4);
    const uint32_t brow = (uint32_t)(wn * 16 + (lane & 15)) * ROW_B
                        + ((lane >> 4) << 4);

    auto compute = [&](int sl) {
        const uint32_t tb = sb + sl * STAGE_B;
#pragma unroll
        for (int h = 0; h < 4; h++) {           // four k16 slices of k64
            uint32_t ah[4], al[4], bh[4], bl[4];
            ldsm4(ah, tb + 0 * TILE_B + arow + h * 32);
            ldsm4(al, tb + 1 * TILE_B + arow + h * 32);
            ldsm4(bh, tb + 2 * TILE_B + brow + h * 32);
            ldsm4(bl, tb + 3 * TILE_B + brow + h * 32);
#pragma unroll
            for (int nf = 0; nf < 2; nf++) {
                float* c = acc[nf];
                mma16816(c, ah, bh[nf], bh[nf + 2]);
                mma16816(c, ah, bl[nf], bl[nf + 2]);
                mma16816(c, al, bh[nf], bh[nf + 2]);
            }
        }
    };

    // ---- 3-stage cp.async pipeline ----
    issue(0, 0);
    asm volatile("cp.async.commit_group;" ::: "memory");
    issue(1, 1);
    asm volatile("cp.async.commit_group;" ::: "memory");

#pragma unroll 1
    for (int kc = 0; kc < NKC; kc++) {
        if (kc + 2 < NKC) issue(kc + 2, (kc + 2) % NSTAGE);
        asm volatile("cp.async.commit_group;" ::: "memory");
        asm volatile("cp.async.wait_group 2;" ::: "memory");
        __syncthreads();
        compute(kc % NSTAGE);
        __syncthreads();
    }

    // ---- epilogue: +bias, crop [1,510], mirror off-diagonal tiles ----
    const float bv = bias[ch];
    const int ib = bi * 32 + wm * 16;
    const int jb = bj * 32 + wn * 16;
    const bool mirror = (bi != bj);

#pragma unroll
    for (int nf = 0; nf < 2; nf++) {
#pragma unroll
        for (int r = 0; r < 4; r++) {
            const int i = ib + (lane >> 2) + ((r >> 1) << 3);
            const int j = jb + nf * 8 + ((lane & 3) << 1) + (r & 1);
            if (i >= 1 && i <= 510 && j >= 1 && j <= 510) {
                const float v = acc[nf][r] + bv;
                out[((size_t)(i - 1) * 510 + (j - 1)) * 2 + ch] = v;
                if (mirror)
                    out[((size_t)(j - 1) * 510 + (i - 1)) * 2 + ch] = v;
            }
        }
    }
}

// ---------------------------------------------------------------------------
extern "C" void kernel_launch(void* const* d_in, const int* in_sizes, int n_in,
                              void* d_out, int out_size)
{
    const float* x = (const float*)d_in[0];   // (1, 512, 768)
    const float* W = (const float*)d_in[1];   // (2, 1536)
    const float* b = (const float*)d_in[2];   // (2,)
    float* out = (float*)d_out;               // (510, 510, 2)

    cudaFuncSetAttribute(pairwise_mma_kernel,
                         cudaFuncAttributeMaxDynamicSharedMemorySize, SMEM_TOTAL);

    prep_kernel<<<(512 * 96 + 255) / 256, 256>>>(x, W);
    pairwise_mma_kernel<<<dim3(16, 16, 2), 128, SMEM_TOTAL>>>(b, out);
}

// round 5
// speedup vs baseline: 3.0587x; 1.3636x over previous
#include <cuda_runtime.h>
#include <cuda_bf16.h>
#include <cstdint>

// out[i,j,o] = sum_h x[i+1,h]*x[j+1,h]*W[o,h] + b[o]
// (diff/W2 term is antisymmetric -> cancels under (P+P^T)/2 symmetrization)
//
// D_o = A_o B^T, A_o = X .* w_o, B = X (512x768 f32)
// fp32 emulated via bf16 hi/lo 3-split on mma.sync m16n8k16.
// Upper-tri 32x32 tiles only (mirror-write), split-K=2 with red.global.add
// (exactly 2 commutative fp32 adds per element onto zeroed buffer ->
//  deterministic). Prep kernel pre-splits bf16 images + zeroes out.

#define HDIM 768
#define KC 64                    // k per chunk (64 bf16 = 128 B rows)
#define NKC_TOT 12               // 768 / 64
#define NKC 6                    // chunks per K-split
#define ROW_B 144                // 128 B data + 16 B pad (conflict-free LDSM)
#define TILE_B (32 * ROW_B)      // 4608 B  (32 rows x 64 bf16)
#define STAGE_B (4 * TILE_B)     // Ahi, Alo, Bhi, Blo = 18432 B
#define NSTAGE 3
#define SMEM_TOTAL (NSTAGE * STAGE_B)   // 55296 B
#define OUT_ELEMS (510 * 510 * 2)

// Pre-split bf16 images: 0:A0hi 1:A0lo 2:A1hi 3:A1lo 4:Bhi 5:Blo
__device__ __nv_bfloat16 g_pre[6][512 * HDIM];

// ---------------------------------------------------------------------------
union Pack8 { __nv_bfloat16 h[8]; uint4 v; };

__device__ __forceinline__ void split8(const float* s, uint4& hi, uint4& lo) {
    Pack8 ph, pl;
#pragma unroll
    for (int t = 0; t < 8; t++) {
        __nv_bfloat16 h = __float2bfloat16(s[t]);
        ph.h[t] = h;
        pl.h[t] = __float2bfloat16(s[t] - __bfloat162float(h));
    }
    hi = ph.v; lo = pl.v;
}

__global__ void prep_kernel(const float* __restrict__ x,
                            const float* __restrict__ W,
                            float* __restrict__ out)
{
    int gid = blockIdx.x * blockDim.x + threadIdx.x;

    // Zero the output buffer (fp32 atomics accumulate into it)
    if (gid < OUT_ELEMS / 4)
        *(float4*)(out + (size_t)gid * 4) = make_float4(0.f, 0.f, 0.f, 0.f);

    if (gid >= 512 * (HDIM / 8)) return;
    int i  = gid / (HDIM / 8);
    int k0 = (gid % (HDIM / 8)) * 8;

    float4 x0 = *(const float4*)(x + (size_t)i * HDIM + k0);
    float4 x1 = *(const float4*)(x + (size_t)i * HDIM + k0 + 4);
    float4 wa0 = *(const float4*)(W + k0);
    float4 wa1 = *(const float4*)(W + k0 + 4);
    float4 wb0 = *(const float4*)(W + 1536 + k0);
    float4 wb1 = *(const float4*)(W + 1536 + k0 + 4);

    float xs[8] = {x0.x, x0.y, x0.z, x0.w, x1.x, x1.y, x1.z, x1.w};
    float w0[8] = {wa0.x, wa0.y, wa0.z, wa0.w, wa1.x, wa1.y, wa1.z, wa1.w};
    float w1[8] = {wb0.x, wb0.y, wb0.z, wb0.w, wb1.x, wb1.y, wb1.z, wb1.w};
    float a0[8], a1[8];
#pragma unroll
    for (int t = 0; t < 8; t++) { a0[t] = xs[t] * w0[t]; a1[t] = xs[t] * w1[t]; }

    uint4 h, l;
    size_t off = (size_t)i * HDIM + k0;
    split8(a0, h, l);
    *(uint4*)(&g_pre[0][off]) = h;  *(uint4*)(&g_pre[1][off]) = l;
    split8(a1, h, l);
    *(uint4*)(&g_pre[2][off]) = h;  *(uint4*)(&g_pre[3][off]) = l;
    split8(xs, h, l);
    *(uint4*)(&g_pre[4][off]) = h;  *(uint4*)(&g_pre[5][off]) = l;
}

// ---------------------------------------------------------------------------
__device__ __forceinline__ uint32_t smem_u32(const void* p) {
    uint32_t a;
    asm("{ .reg .u64 t; cvta.to.shared.u64 t, %1; cvt.u32.u64 %0, t; }"
        : "=r"(a) : "l"(p));
    return a;
}

__device__ __forceinline__ void cp16(uint32_t dst, const void* src) {
    asm volatile("cp.async.cg.shared.global [%0], [%1], 16;"
                 :: "r"(dst), "l"(src) : "memory");
}

__device__ __forceinline__ void ldsm4(uint32_t* r, uint32_t addr) {
    asm volatile("ldmatrix.sync.aligned.m8n8.x4.shared.b16 {%0,%1,%2,%3}, [%4];"
                 : "=r"(r[0]), "=r"(r[1]), "=r"(r[2]), "=r"(r[3]) : "r"(addr));
}

__device__ __forceinline__ void mma16816(float* c, const uint32_t* a,
                                         uint32_t b0, uint32_t b1) {
    asm volatile(
        "mma.sync.aligned.m16n8k16.row.col.f32.bf16.bf16.f32 "
        "{%0,%1,%2,%3}, {%4,%5,%6,%7}, {%8,%9}, {%0,%1,%2,%3};"
        : "+f"(c[0]), "+f"(c[1]), "+f"(c[2]), "+f"(c[3])
        : "r"(a[0]), "r"(a[1]), "r"(a[2]), "r"(a[3]), "r"(b0), "r"(b1));
}

__device__ __forceinline__ void red_add(float* p, float v) {
    asm volatile("red.global.add.f32 [%0], %1;" :: "l"(p), "f"(v) : "memory");
}

__global__ void __launch_bounds__(128)
pairwise_mma_kernel(const float* __restrict__ bias, float* __restrict__ out)
{
    // Triangular decode: blockIdx.x in [0,136) -> (bi, bj) with bj >= bi
    int t = blockIdx.x;
    int bi = 0;
    while (t >= 16 - bi) { t -= 16 - bi; bi++; }
    const int bj = bi + t;
    const int ch = blockIdx.y;
    const int ks = blockIdx.z;          // K split (0/1)

    extern __shared__ __align__(16) char smem[];
    const uint32_t sb = smem_u32(smem);

    const int tid  = threadIdx.x;
    const int wid  = tid >> 5;
    const int lane = tid & 31;
    const int wm = wid >> 1;          // warp row (0..1) of 16
    const int wn = wid & 1;           // warp col (0..1) of 16

    const __nv_bfloat16* src[4];
    src[0] = &g_pre[ch * 2 + 0][(size_t)(bi * 32) * HDIM];
    src[1] = &g_pre[ch * 2 + 1][(size_t)(bi * 32) * HDIM];
    src[2] = &g_pre[4][(size_t)(bj * 32) * HDIM];
    src[3] = &g_pre[5][(size_t)(bj * 32) * HDIM];

    const int lrow = tid >> 3;        // 0..15
    const int lc   = tid & 7;         // 16B chunk within 128B row
    const int kc0  = ks * NKC;        // first chunk of this split

    auto issue = [&](int kc, int sl) {
        const uint32_t dbase = sb + sl * STAGE_B + lc * 16;
        const int kcol = (kc0 + kc) * KC + lc * 8;
#pragma unroll
        for (int q = 0; q < 4; q++) {
#pragma unroll
            for (int p = 0; p < 2; p++) {
                const int row = lrow + p * 16;
                cp16(dbase + q * TILE_B + row * ROW_B,
                     src[q] + (size_t)row * HDIM + kcol);
            }
        }
    };

    // Three independent split chains: 0=hh, 1=hl, 2=lh
    float acc[3][2][4] = {};

    const uint32_t arow = (uint32_t)(wm * 16 + (lane & 15)) * ROW_B
                        + ((lane >> 4) << 4);
    const uint32_t brow = (uint32_t)(wn * 16 + (lane & 15)) * ROW_B
                        + ((lane >> 4) << 4);

    auto compute = [&](int sl) {
        const uint32_t tb = sb + sl * STAGE_B;
#pragma unroll
        for (int h = 0; h < 4; h++) {           // four k16 slices of k64
            uint32_t ah[4], al[4], bh[4], bl[4];
            ldsm4(ah, tb + 0 * TILE_B + arow + h * 32);
            ldsm4(al, tb + 1 * TILE_B + arow + h * 32);
            ldsm4(bh, tb + 2 * TILE_B + brow + h * 32);
            ldsm4(bl, tb + 3 * TILE_B + brow + h * 32);
#pragma unroll
            for (int nf = 0; nf < 2; nf++) {
                mma16816(acc[0][nf], ah, bh[nf], bh[nf + 2]);
                mma16816(acc[1][nf], ah, bl[nf], bl[nf + 2]);
                mma16816(acc[2][nf], al, bh[nf], bh[nf + 2]);
            }
        }
    };

    // ---- 3-stage cp.async pipeline over 6 chunks ----
    issue(0, 0);
    asm volatile("cp.async.commit_group;" ::: "memory");
    issue(1, 1);
    asm volatile("cp.async.commit_group;" ::: "memory");

#pragma unroll 1
    for (int kc = 0; kc < NKC; kc++) {
        if (kc + 2 < NKC) issue(kc + 2, (kc + 2) % NSTAGE);
        asm volatile("cp.async.commit_group;" ::: "memory");
        asm volatile("cp.async.wait_group 2;" ::: "memory");
        __syncthreads();
        compute(kc % NSTAGE);
        __syncthreads();
    }

    // ---- epilogue: half-bias per split, crop [1,510], mirror, red.add ----
    const float bv = bias[ch] * 0.5f;
    const int ib = bi * 32 + wm * 16;
    const int jb = bj * 32 + wn * 16;
    const bool mirror = (bi != bj);

#pragma unroll
    for (int nf = 0; nf < 2; nf++) {
#pragma unroll
        for (int r = 0; r < 4; r++) {
            const int i = ib + (lane >> 2) + ((r >> 1) << 3);
            const int j = jb + nf * 8 + ((lane & 3) << 1) + (r & 1);
            if (i >= 1 && i <= 510 && j >= 1 && j <= 510) {
                const float v = acc[0][nf][r] + acc[1][nf][r]
                              + acc[2][nf][r] + bv;
                red_add(out + ((size_t)(i - 1) * 510 + (j - 1)) * 2 + ch, v);
                if (mirror)
                    red_add(out + ((size_t)(j - 1) * 510 + (i - 1)) * 2 + ch, v);
            }
        }
    }
}

// ---------------------------------------------------------------------------
extern "C" void kernel_launch(void* const* d_in, const int* in_sizes, int n_in,
                              void* d_out, int out_size)
{
    const float* x = (const float*)d_in[0];   // (1, 512, 768)
    const float* W = (const float*)d_in[1];   // (2, 1536)
    const float* b = (const float*)d_in[2];   // (2,)
    float* out = (float*)d_out;               // (510, 510, 2)

    cudaFuncSetAttribute(pairwise_mma_kernel,
                         cudaFuncAttributeMaxDynamicSharedMemorySize, SMEM_TOTAL);

    // prep + out-zeroing: need max(49152, 130050) threads
    prep_kernel<<<(OUT_ELEMS / 4 + 255) / 256, 256>>>(x, W, out);
    pairwise_mma_kernel<<<dim3(136, 2, 2), 128, SMEM_TOTAL>>>(b, out);
}